// round 15
// baseline (speedup 1.0000x reference)
#include <cuda_runtime.h>
#include <math.h>
#include <stdint.h>

// Problem constants
#define NN   50000
#define EE   800000
#define RR   2
#define LL   4
#define CIN  64
#define HID  128
#define NH   8
#define HD   16
#define COUT 32

#define GATW (LL * RR * HID * HID)   // 131072 gat fc elements

// ---------------- scratch (device globals; no allocation allowed) ----------
__device__ float g_t0[NN * HID];
__device__ float g_h1[NN * HID];
__device__ float g_feat[RR * NN * HID];
__device__ float g_el[RR * NN * NH];
__device__ float g_er[RR * NN * NH];
__device__ float g_stat[2 * HID];
__device__ float g_scale[HID];
__device__ float g_shift[HID];
__device__ uint2 g_wsplit[GATW];
// CSR scratch
__device__ int g_deg[RR * NN];
__device__ int g_cur[RR * NN];
__device__ int g_off[RR * (NN + 1)];
__device__ int g_csrc[RR * EE];

// ---------------- helpers ---------------------------------------------------
__device__ __forceinline__ float lrelu02(float x) { return x > 0.f ? x : 0.2f * x; }

__device__ __forceinline__ uint32_t f2tf32(float f) {
    uint32_t r;
    asm("cvt.rna.tf32.f32 %0, %1;" : "=r"(r) : "f"(f));
    return r;
}
// split x into interleaved (hi, lo) tf32 pair
__device__ __forceinline__ uint2 split2(float x) {
    uint2 p;
    p.x = f2tf32(x);
    p.y = f2tf32(x - __uint_as_float(p.x));
    return p;
}

__device__ __forceinline__ void mma_tf32(float4& d, const uint32_t* a, const uint32_t* b) {
    asm volatile(
        "mma.sync.aligned.m16n8k8.row.col.f32.tf32.tf32.f32 "
        "{%0,%1,%2,%3}, {%4,%5,%6,%7}, {%8,%9}, {%0,%1,%2,%3};"
        : "+f"(d.x), "+f"(d.y), "+f"(d.z), "+f"(d.w)
        : "r"(a[0]), "r"(a[1]), "r"(a[2]), "r"(a[3]), "r"(b[0]), "r"(b[1]));
}

// ---------------- GAT weight pre-split: float -> (hi,lo) tf32 uint2 ---------
__global__ void wsplit_kernel(const float* __restrict__ w, uint2* __restrict__ out) {
    int i = blockIdx.x * blockDim.x + threadIdx.x;
    if (i < GATW) out[i] = split2(w[i]);
}

// ---------------- 3xTF32 tensor-core GEMM ------------------------------------
// C[n,128] = op(A)[n,KIN] @ W[KIN,128].
// WSP=false: W raw float, split in-kernel (register-staged).
// WSP=true:  W pre-split uint2 table (Wsp), direct global->smem copy.
// blockIdx.y selects relation (offsets W/C and attl/attr/el/er when ELR).
// BM=128, BN=128, BK=32. 256 threads = 8 warps (4M x 2N), warp tile 32x64.
template <int KIN, bool ADD_A, bool BNA, bool ELR, bool WSP>
__global__ __launch_bounds__(256) void gemm_tf32_kernel(
    const float* __restrict__ A, const float* __restrict__ W,
    const uint2* __restrict__ Wsp, float* __restrict__ C, int n,
    const float* __restrict__ bnscale, const float* __restrict__ bnshift,
    const float* __restrict__ attl, const float* __restrict__ attr,
    float* __restrict__ el, float* __restrict__ er) {
    constexpr int KT = KIN / 32;
    constexpr int AS = 34;   // uint2 stride per A row
    constexpr int WS = 132;  // uint2 stride per W row
    __shared__ uint2 As2[128 * AS];
    __shared__ uint2 Ws2[32 * WS];

    const int rel = blockIdx.y;
    if (WSP) Wsp += (size_t)rel * KIN * 128;
    else W += (size_t)rel * KIN * 128;
    C += (size_t)rel * NN * 128;
    if (ELR) {
        attl += rel * NH * HD;
        attr += rel * NH * HD;
        el += (size_t)rel * NN * NH;
        er += (size_t)rel * NN * NH;
    }

    const int tid = threadIdx.x;
    const int wid = tid >> 5;
    const int lane = tid & 31;
    const int wr = wid & 3;
    const int wc = wid >> 2;
    const int gr = lane >> 2;
    const int gc = lane & 3;
    const int m0 = blockIdx.x * 128;

    float4 acc[2][8];
#pragma unroll
    for (int mt = 0; mt < 2; mt++)
#pragma unroll
        for (int nt = 0; nt < 8; nt++) acc[mt][nt] = make_float4(0.f, 0.f, 0.f, 0.f);

    float4 ra[4], rw[4];

    auto ldA = [&](int row, int col4) -> float4 {
        float4 v = make_float4(0.f, 0.f, 0.f, 0.f);
        if (m0 + row < n) v = *(const float4*)&A[(size_t)(m0 + row) * KIN + col4];
        if (BNA) {
            float4 sc = *(const float4*)&bnscale[col4];
            float4 sh = *(const float4*)&bnshift[col4];
            v.x = fmaxf(0.f, v.x * sc.x + sh.x);
            v.y = fmaxf(0.f, v.y * sc.y + sh.y);
            v.z = fmaxf(0.f, v.z * sc.z + sh.z);
            v.w = fmaxf(0.f, v.w * sc.w + sh.w);
        }
        return v;
    };

    // ---- prefetch tile 0 (A always; W staged only when splitting in-kernel)
#pragma unroll
    for (int t = 0; t < 4; t++) {
        int f = tid + t * 256;
        int row = f >> 3, c4 = f & 7;
        ra[t] = ldA(row, c4 * 4);
        if (!WSP) {
            int wrow = f >> 5, wc4 = f & 31;
            rw[t] = *(const float4*)&W[(size_t)wrow * 128 + wc4 * 4];
        }
    }

    for (int kt = 0; kt < KT; kt++) {
#pragma unroll
        for (int t = 0; t < 4; t++) {
            int f = tid + t * 256;
            int row = f >> 3, c4 = f & 7;
            uint2* p = &As2[row * AS + c4 * 4];
            p[0] = split2(ra[t].x);
            p[1] = split2(ra[t].y);
            p[2] = split2(ra[t].z);
            p[3] = split2(ra[t].w);
            int wrow = f >> 5, wc4 = f & 31;
            if (WSP) {
                const uint4* wsrc =
                    (const uint4*)&Wsp[(size_t)(kt * 32 + wrow) * 128 + wc4 * 4];
                uint4 w0 = wsrc[0];
                uint4 w1 = wsrc[1];
                *(uint4*)&Ws2[wrow * WS + wc4 * 4] = w0;
                *(uint4*)&Ws2[wrow * WS + wc4 * 4 + 2] = w1;
            } else {
                uint2* q = &Ws2[wrow * WS + wc4 * 4];
                q[0] = split2(rw[t].x);
                q[1] = split2(rw[t].y);
                q[2] = split2(rw[t].z);
                q[3] = split2(rw[t].w);
            }
        }
        __syncthreads();

        if (kt + 1 < KT) {
            int kbase = (kt + 1) * 32;
#pragma unroll
            for (int t = 0; t < 4; t++) {
                int f = tid + t * 256;
                int row = f >> 3, c4 = f & 7;
                ra[t] = ldA(row, kbase + c4 * 4);
                if (!WSP) {
                    int wrow = f >> 5, wc4 = f & 31;
                    rw[t] = *(const float4*)&W[(size_t)(kbase + wrow) * 128 + wc4 * 4];
                }
            }
        }

#pragma unroll
        for (int k8 = 0; k8 < 4; k8++) {
            int k0 = k8 * 8;
            uint32_t ah[2][4], alo[2][4];
#pragma unroll
            for (int mt = 0; mt < 2; mt++) {
                int base = wr * 32 + mt * 16;
                uint2 x00 = As2[(base + gr) * AS + k0 + gc];
                uint2 x10 = As2[(base + gr + 8) * AS + k0 + gc];
                uint2 x01 = As2[(base + gr) * AS + k0 + gc + 4];
                uint2 x11 = As2[(base + gr + 8) * AS + k0 + gc + 4];
                ah[mt][0] = x00.x; alo[mt][0] = x00.y;
                ah[mt][1] = x10.x; alo[mt][1] = x10.y;
                ah[mt][2] = x01.x; alo[mt][2] = x01.y;
                ah[mt][3] = x11.x; alo[mt][3] = x11.y;
            }
#pragma unroll
            for (int nt = 0; nt < 8; nt++) {
                int col = wc * 64 + nt * 8 + gr;
                uint2 y0 = Ws2[(k0 + gc) * WS + col];
                uint2 y1 = Ws2[(k0 + gc + 4) * WS + col];
                uint32_t bh[2] = {y0.x, y1.x};
                uint32_t bl[2] = {y0.y, y1.y};
#pragma unroll
                for (int mt = 0; mt < 2; mt++) {
                    mma_tf32(acc[mt][nt], ah[mt], bh);   // hi*hi
                    mma_tf32(acc[mt][nt], alo[mt], bh);  // lo*hi
                    mma_tf32(acc[mt][nt], ah[mt], bl);   // hi*lo
                }
            }
        }
        __syncthreads();
    }

    // ---- epilogue
#pragma unroll
    for (int mt = 0; mt < 2; mt++) {
        int row0 = m0 + wr * 32 + mt * 16 + gr;
        int row1 = row0 + 8;
#pragma unroll
        for (int nt = 0; nt < 8; nt++) {
            int col = wc * 64 + nt * 8 + 2 * gc;
            float4 v = acc[mt][nt];
            if (row0 < n) {
                float2 o = make_float2(v.x, v.y);
                if (ADD_A) {
                    float2 a = *(const float2*)&A[(size_t)row0 * KIN + col];
                    if (BNA) {
                        a.x = fmaxf(0.f, a.x * bnscale[col] + bnshift[col]);
                        a.y = fmaxf(0.f, a.y * bnscale[col + 1] + bnshift[col + 1]);
                    }
                    o.x += a.x; o.y += a.y;
                }
                *(float2*)&C[(size_t)row0 * 128 + col] = o;
            }
            if (row1 < n) {
                float2 o = make_float2(v.z, v.w);
                if (ADD_A) {
                    float2 a = *(const float2*)&A[(size_t)row1 * KIN + col];
                    if (BNA) {
                        a.x = fmaxf(0.f, a.x * bnscale[col] + bnshift[col]);
                        a.y = fmaxf(0.f, a.y * bnscale[col + 1] + bnshift[col + 1]);
                    }
                    o.x += a.x; o.y += a.y;
                }
                *(float2*)&C[(size_t)row1 * 128 + col] = o;
            }
        }
    }

    // ---- fused attention-logit epilogue
    if (ELR) {
#pragma unroll
        for (int j = 0; j < 4; j++) {
            int head = wc * 4 + j;
            const float* alh = attl + head * 16;
            const float* arh = attr + head * 16;
            float al0 = alh[2 * gc],     al1 = alh[2 * gc + 1];
            float al2 = alh[8 + 2 * gc], al3 = alh[8 + 2 * gc + 1];
            float ar0 = arh[2 * gc],     ar1 = arh[2 * gc + 1];
            float ar2 = arh[8 + 2 * gc], ar3 = arh[8 + 2 * gc + 1];
            float sl[4], sr[4];
#pragma unroll
            for (int mt = 0; mt < 2; mt++) {
                float4 v0 = acc[mt][2 * j];
                float4 v1 = acc[mt][2 * j + 1];
                sl[mt * 2 + 0] = v0.x * al0 + v0.y * al1 + v1.x * al2 + v1.y * al3;
                sl[mt * 2 + 1] = v0.z * al0 + v0.w * al1 + v1.z * al2 + v1.w * al3;
                sr[mt * 2 + 0] = v0.x * ar0 + v0.y * ar1 + v1.x * ar2 + v1.y * ar3;
                sr[mt * 2 + 1] = v0.z * ar0 + v0.w * ar1 + v1.z * ar2 + v1.w * ar3;
            }
#pragma unroll
            for (int i = 0; i < 4; i++) {
                sl[i] += __shfl_xor_sync(0xFFFFFFFFu, sl[i], 1);
                sl[i] += __shfl_xor_sync(0xFFFFFFFFu, sl[i], 2);
                sr[i] += __shfl_xor_sync(0xFFFFFFFFu, sr[i], 1);
                sr[i] += __shfl_xor_sync(0xFFFFFFFFu, sr[i], 2);
            }
            if (gc == 0) {
#pragma unroll
                for (int mt = 0; mt < 2; mt++) {
                    int r0 = m0 + wr * 32 + mt * 16 + gr;
                    int r1 = r0 + 8;
                    if (r0 < n) { el[r0 * 8 + head] = sl[mt * 2 + 0]; er[r0 * 8 + head] = sr[mt * 2 + 0]; }
                    if (r1 < n) { el[r1 * 8 + head] = sl[mt * 2 + 1]; er[r1 * 8 + head] = sr[mt * 2 + 1]; }
                }
            }
        }
    }
}

// ---------------- scalar fp32 GEMM (KOUT=32 decode head, fused BN on A) -----
template <int KIN, int KOUT, bool BNA>
__global__ void gemm_kernel(const float* __restrict__ A, const float* __restrict__ W,
                            float* __restrict__ C, int n,
                            const float* __restrict__ bnscale,
                            const float* __restrict__ bnshift) {
    constexpr int BM = 128, BK = 32;
    constexpr int TN = KOUT / 16;
    __shared__ float As[BK][BM + 4];
    __shared__ float Ws[BK][KOUT];

    const int tid = threadIdx.x;
    const int ty = tid >> 4;
    const int tx = tid & 15;
    const int m0 = blockIdx.x * BM;

    float acc[8][TN];
#pragma unroll
    for (int i = 0; i < 8; i++)
#pragma unroll
        for (int j = 0; j < TN; j++) acc[i][j] = 0.f;

    for (int kt = 0; kt < KIN; kt += BK) {
        for (int q = tid; q < (BM * BK) / 4; q += 256) {
            int row = q / (BK / 4);
            int c4 = q % (BK / 4);
            float4 v = make_float4(0.f, 0.f, 0.f, 0.f);
            if (m0 + row < n)
                v = *(const float4*)&A[(size_t)(m0 + row) * KIN + kt + c4 * 4];
            if (BNA) {
                int col = kt + c4 * 4;
                float4 sc = *(const float4*)&bnscale[col];
                float4 sh = *(const float4*)&bnshift[col];
                v.x = fmaxf(0.f, v.x * sc.x + sh.x);
                v.y = fmaxf(0.f, v.y * sc.y + sh.y);
                v.z = fmaxf(0.f, v.z * sc.z + sh.z);
                v.w = fmaxf(0.f, v.w * sc.w + sh.w);
            }
            As[c4 * 4 + 0][row] = v.x;
            As[c4 * 4 + 1][row] = v.y;
            As[c4 * 4 + 2][row] = v.z;
            As[c4 * 4 + 3][row] = v.w;
        }
        for (int q = tid; q < (BK * KOUT) / 4; q += 256) {
            int row = q / (KOUT / 4);
            int c4 = q % (KOUT / 4);
            *(float4*)&Ws[row][c4 * 4] = *(const float4*)&W[(size_t)(kt + row) * KOUT + c4 * 4];
        }
        __syncthreads();
#pragma unroll
        for (int kk = 0; kk < BK; kk++) {
            float a[8], w[TN];
#pragma unroll
            for (int i = 0; i < 8; i++) a[i] = As[kk][ty * 8 + i];
#pragma unroll
            for (int j = 0; j < TN; j++) w[j] = Ws[kk][tx * TN + j];
#pragma unroll
            for (int i = 0; i < 8; i++)
#pragma unroll
                for (int j = 0; j < TN; j++) acc[i][j] = fmaf(a[i], w[j], acc[i][j]);
        }
        __syncthreads();
    }
#pragma unroll
    for (int i = 0; i < 8; i++) {
        int row = m0 + ty * 8 + i;
        if (row < n) {
#pragma unroll
            for (int j = 0; j < TN; j++) {
                int col = tx * TN + j;
                C[(size_t)row * KOUT + col] = acc[i][j];
            }
        }
    }
}

// ---------------- BN statistics --------------------------------------------
__global__ void stats_kernel(const float* __restrict__ X, float* __restrict__ stat, int n) {
    int c = threadIdx.x;
    int row0 = blockIdx.x * 128;
    float s = 0.f, s2 = 0.f;
#pragma unroll 4
    for (int i = 0; i < 128; i++) {
        int r = row0 + i;
        if (r < n) {
            float v = X[(size_t)r * HID + c];
            s += v;
            s2 += v * v;
        }
    }
    atomicAdd(&stat[c], s);
    atomicAdd(&stat[HID + c], s2);
}

__global__ void stats_final_kernel(const float* __restrict__ stat,
                                   const float* __restrict__ gamma,
                                   const float* __restrict__ beta,
                                   float* __restrict__ scale, float* __restrict__ shift,
                                   int n) {
    int c = threadIdx.x;
    float m = stat[c] / (float)n;
    float var = stat[HID + c] / (float)n - m * m;
    float rs = rsqrtf(var + 1e-5f) * gamma[c];
    scale[c] = rs;
    shift[c] = beta[c] - m * rs;
}

// ---------------- CSR build --------------------------------------------------
__global__ void hist_kernel(const int* __restrict__ dst, int* __restrict__ deg) {
    int i = blockIdx.x * blockDim.x + threadIdx.x;
    if (i >= RR * EE) return;
    int r = i / EE;
    atomicAdd(&deg[r * NN + dst[i]], 1);
}

__global__ void scan_kernel(const int* __restrict__ deg, int* __restrict__ off) {
    const int rel = blockIdx.x;
    const int* d = deg + rel * NN;
    int* o = off + rel * (NN + 1);
    const int T = 1024;
    const int tid = threadIdx.x;
    const int CH = (NN + T - 1) / T;
    int base = tid * CH;

    int s = 0;
    for (int j = 0; j < CH; j++) {
        int idx = base + j;
        if (idx < NN) s += d[idx];
    }
    int lane = tid & 31, wid = tid >> 5;
    int v = s;
#pragma unroll
    for (int ofs = 1; ofs < 32; ofs <<= 1) {
        int t = __shfl_up_sync(0xFFFFFFFFu, v, ofs);
        if (lane >= ofs) v += t;
    }
    __shared__ int ws[32];
    if (lane == 31) ws[wid] = v;
    __syncthreads();
    if (wid == 0) {
        int w = ws[lane];
#pragma unroll
        for (int ofs = 1; ofs < 32; ofs <<= 1) {
            int t = __shfl_up_sync(0xFFFFFFFFu, w, ofs);
            if (lane >= ofs) w += t;
        }
        ws[lane] = w;
    }
    __syncthreads();
    int excl = v - s + (wid > 0 ? ws[wid - 1] : 0);

    int run = excl;
    for (int j = 0; j < CH; j++) {
        int idx = base + j;
        if (idx < NN) {
            o[idx] = run;
            run += d[idx];
        }
    }
    if (tid == T - 1) o[NN] = run;
}

__global__ void fill_kernel(const int* __restrict__ src, const int* __restrict__ dst,
                            const int* __restrict__ off, int* __restrict__ cur,
                            int* __restrict__ csrc) {
    int i = blockIdx.x * blockDim.x + threadIdx.x;
    if (i >= RR * EE) return;
    int r = i / EE;
    int d = dst[i];
    int pos = atomicAdd(&cur[r * NN + d], 1);
    csrc[(size_t)r * EE + off[r * (NN + 1) + d] + pos] = src[i];
}

// ---------------- fused GAT: both relations, online softmax, residual -------
// warp per dst node; h1 += leakyrelu(sum_r rst_r + b0 + b1, 0.01)
__global__ void gat_fused_kernel(const int* __restrict__ off, const int* __restrict__ csrc,
                                 const float* __restrict__ elA, const float* __restrict__ erA,
                                 const float* __restrict__ featA,
                                 const float* __restrict__ b0, const float* __restrict__ b1,
                                 float* __restrict__ h1) {
    const int node = blockIdx.x * (blockDim.x >> 5) + (threadIdx.x >> 5);
    const int lane = threadIdx.x & 31;
    if (node >= NN) return;

    const int h = lane >> 2;
    const int k = lane & 3;

    float4 a4 = make_float4(0.f, 0.f, 0.f, 0.f);

#pragma unroll
    for (int r = 0; r < 2; r++) {
        const int* offr = off + r * (NN + 1);
        const int* cs = csrc + (size_t)r * EE;
        const float* el = elA + (size_t)r * NN * NH;
        const float* er = erA + (size_t)r * NN * NH;
        const float* feat = featA + (size_t)r * NN * HID;

        const int beg = offr[node];
        const int end = offr[node + 1];
        const float er_h = er[node * 8 + h];

        // online max + exp-sum (single pass over edges)
        float m = -INFINITY, s = 0.f;
        for (int e = beg + k; e < end; e += 4) {
            int si = cs[e];
            float v = lrelu02(el[si * 8 + h] + er_h);
            float mn = fmaxf(m, v);
            s = s * __expf(m - mn) + __expf(v - mn);
            m = mn;
        }
        // combine across 4 sublanes — NaN-safe: factor is 0 when m == -inf
#pragma unroll
        for (int ofs = 1; ofs < 4; ofs <<= 1) {
            float om = __shfl_xor_sync(0xFFFFFFFFu, m, ofs);
            float os = __shfl_xor_sync(0xFFFFFFFFu, s, ofs);
            float mn = fmaxf(m, om);
            float f1 = (m > -INFINITY) ? __expf(m - mn) : 0.f;
            float f2 = (om > -INFINITY) ? __expf(om - mn) : 0.f;
            s = s * f1 + os * f2;
            m = mn;
        }

        float m_l = __shfl_sync(0xFFFFFFFFu, m, (lane & 7) * 4);
        float inv_l = 1.0f / __shfl_sync(0xFFFFFFFFu, s, (lane & 7) * 4);
        float er_l = (lane < 8) ? er[node * 8 + lane] : 0.f;

        const float4* feat4 = (const float4*)feat;
        for (int e = beg; e < end; e++) {
            int si = cs[e];
            float alpha = 0.f;
            if (lane < 8) {
                float v = lrelu02(el[si * 8 + lane] + er_l);
                alpha = __expf(v - m_l) * inv_l;
            }
            float a = __shfl_sync(0xFFFFFFFFu, alpha, lane >> 2);
            float4 f = feat4[(size_t)si * 32 + lane];
            a4.x = fmaf(a, f.x, a4.x);
            a4.y = fmaf(a, f.y, a4.y);
            a4.z = fmaf(a, f.z, a4.z);
            a4.w = fmaf(a, f.w, a4.w);
        }
    }

    float4 c0 = ((const float4*)b0)[lane];
    float4 c1 = ((const float4*)b1)[lane];
    float4 hv = ((const float4*)h1)[(size_t)node * 32 + lane];
    float vx = a4.x + c0.x + c1.x;
    float vy = a4.y + c0.y + c1.y;
    float vz = a4.z + c0.z + c1.z;
    float vw = a4.w + c0.w + c1.w;
    vx = vx > 0.f ? vx : 0.01f * vx;
    vy = vy > 0.f ? vy : 0.01f * vy;
    vz = vz > 0.f ? vz : 0.01f * vz;
    vw = vw > 0.f ? vw : 0.01f * vw;
    ((float4*)h1)[(size_t)node * 32 + lane] =
        make_float4(hv.x + vx, hv.y + vy, hv.z + vz, hv.w + vw);
}

// ---------------- host orchestration ----------------------------------------
extern "C" void kernel_launch(void* const* d_in, const int* in_sizes, int n_in,
                              void* d_out, int out_size) {
    const float* inputs     = (const float*)d_in[0];
    const int*   src        = (const int*)d_in[1];
    const int*   dst        = (const int*)d_in[2];
    const float* embed_w1   = (const float*)d_in[3];
    const float* embed_g    = (const float*)d_in[4];
    const float* embed_b    = (const float*)d_in[5];
    const float* embed_w2   = (const float*)d_in[6];
    const float* gat_fc     = (const float*)d_in[7];
    const float* gat_al     = (const float*)d_in[8];
    const float* gat_ar     = (const float*)d_in[9];
    const float* gat_bias   = (const float*)d_in[10];
    const float* dec_w1     = (const float*)d_in[11];
    const float* dec_g      = (const float*)d_in[12];
    const float* dec_b      = (const float*)d_in[13];
    const float* dec_w2     = (const float*)d_in[14];
    float* out = (float*)d_out;

    float *t0, *h1, *feat, *el, *er, *stat, *scale, *shift;
    uint2* wsplit;
    int *deg, *cur, *off, *csrc;
    cudaGetSymbolAddress((void**)&t0, g_t0);
    cudaGetSymbolAddress((void**)&h1, g_h1);
    cudaGetSymbolAddress((void**)&feat, g_feat);
    cudaGetSymbolAddress((void**)&el, g_el);
    cudaGetSymbolAddress((void**)&er, g_er);
    cudaGetSymbolAddress((void**)&stat, g_stat);
    cudaGetSymbolAddress((void**)&scale, g_scale);
    cudaGetSymbolAddress((void**)&shift, g_shift);
    cudaGetSymbolAddress((void**)&wsplit, g_wsplit);
    cudaGetSymbolAddress((void**)&deg, g_deg);
    cudaGetSymbolAddress((void**)&cur, g_cur);
    cudaGetSymbolAddress((void**)&off, g_off);
    cudaGetSymbolAddress((void**)&csrc, g_csrc);

    // side stream + fork/join events (created once; host-side only)
    static cudaStream_t s2 = nullptr;
    static cudaEvent_t ev_fork = nullptr, ev_w = nullptr, ev_join = nullptr;
    if (s2 == nullptr) {
        cudaStreamCreateWithFlags(&s2, cudaStreamNonBlocking);
        cudaEventCreateWithFlags(&ev_fork, cudaEventDisableTiming);
        cudaEventCreateWithFlags(&ev_w, cudaEventDisableTiming);
        cudaEventCreateWithFlags(&ev_join, cudaEventDisableTiming);
    }

    const int gemm_grid = (NN + 127) / 128;          // 391
    const int e2_grid   = (RR * EE + 255) / 256;     // 6250
    const int gat_grid  = (NN + 7) / 8;              // 6250 (8 warps/block)

    // ---- fork: GAT weight pre-split + CSR build on side stream
    cudaEventRecord(ev_fork, 0);
    cudaStreamWaitEvent(s2, ev_fork, 0);
    wsplit_kernel<<<(GATW + 255) / 256, 256, 0, s2>>>(gat_fc, wsplit);
    cudaEventRecord(ev_w, s2);
    cudaMemsetAsync(deg, 0, RR * NN * sizeof(int), s2);
    cudaMemsetAsync(cur, 0, RR * NN * sizeof(int), s2);
    hist_kernel<<<e2_grid, 256, 0, s2>>>(dst, deg);
    scan_kernel<<<RR, 1024, 0, s2>>>(deg, off);
    fill_kernel<<<e2_grid, 256, 0, s2>>>(src, dst, off, cur, csrc);
    cudaEventRecord(ev_join, s2);

    // ---- embed: t0 = x @ w1 ; bn stats ; h1 = bn(t0) @ w2 + bn(t0)  (main stream)
    gemm_tf32_kernel<CIN, false, false, false, false><<<gemm_grid, 256>>>(
        inputs, embed_w1, nullptr, t0, NN, nullptr, nullptr, nullptr, nullptr, nullptr,
        nullptr);
    cudaMemsetAsync(stat, 0, 2 * HID * sizeof(float));
    stats_kernel<<<gemm_grid, 128>>>(t0, stat, NN);
    stats_final_kernel<<<1, HID>>>(stat, embed_g, embed_b, scale, shift, NN);
    gemm_tf32_kernel<HID, true, true, false, false><<<gemm_grid, 256>>>(
        t0, embed_w2, nullptr, h1, NN, scale, shift, nullptr, nullptr, nullptr, nullptr);

    // ---- GAT layers: both-relation fc GEMM (pre-split W, fused el/er), then edge kernel
    for (int l = 0; l < LL; l++) {
        if (l == 0) cudaStreamWaitEvent(0, ev_w, 0);  // wsplit table ready
        dim3 grid2(gemm_grid, RR);
        gemm_tf32_kernel<HID, false, false, true, true><<<grid2, 256>>>(
            h1, nullptr, wsplit + (size_t)l * RR * HID * HID, feat, NN, nullptr, nullptr,
            gat_al + (size_t)l * RR * NH * HD, gat_ar + (size_t)l * RR * NH * HD, el, er);
        if (l == 0) cudaStreamWaitEvent(0, ev_join, 0);  // CSR ready
        const float* b0 = gat_bias + (size_t)(l * RR + 0) * HID;
        const float* b1 = gat_bias + (size_t)(l * RR + 1) * HID;
        gat_fused_kernel<<<gat_grid, 256>>>(off, csrc, el, er, feat, b0, b1, h1);
    }

    // ---- decode: t0 = h1 @ w1 ; bn stats ; out = bn(t0) @ w2
    gemm_tf32_kernel<HID, false, false, false, false><<<gemm_grid, 256>>>(
        h1, dec_w1, nullptr, t0, NN, nullptr, nullptr, nullptr, nullptr, nullptr, nullptr);
    cudaMemsetAsync(stat, 0, 2 * HID * sizeof(float));
    stats_kernel<<<gemm_grid, 128>>>(t0, stat, NN);
    stats_final_kernel<<<1, HID>>>(stat, dec_g, dec_b, scale, shift, NN);
    gemm_kernel<HID, COUT, true><<<gemm_grid, 256>>>(t0, dec_w2, out, NN, scale, shift);
}

// round 16
// speedup vs baseline: 1.0415x; 1.0415x over previous
#include <cuda_runtime.h>
#include <math.h>
#include <stdint.h>

// Problem constants
#define NN   50000
#define EE   800000
#define RR   2
#define LL   4
#define CIN  64
#define HID  128
#define NH   8
#define HD   16
#define COUT 32

// ---------------- scratch (device globals; no allocation allowed) ----------
__device__ float g_t0[NN * HID];
__device__ float g_h1[NN * HID];
__device__ float g_feat[RR * NN * HID];
__device__ float g_el[RR * NN * NH];
__device__ float g_er[RR * NN * NH];
__device__ float g_stat[4 * HID];   // [0:2H) embed sum/sumsq, [2H:4H) decode
__device__ float g_scale[HID];
__device__ float g_shift[HID];
// CSR scratch
__device__ int g_deg[RR * NN];
__device__ int g_cur[RR * NN];
__device__ int g_off[RR * (NN + 1)];
__device__ int g_csrc[RR * EE];

// ---------------- helpers ---------------------------------------------------
__device__ __forceinline__ float lrelu02(float x) { return x > 0.f ? x : 0.2f * x; }

__device__ __forceinline__ uint32_t f2tf32(float f) {
    uint32_t r;
    asm("cvt.rna.tf32.f32 %0, %1;" : "=r"(r) : "f"(f));
    return r;
}
// split x into interleaved (hi, lo) tf32 pair
__device__ __forceinline__ uint2 split2(float x) {
    uint2 p;
    p.x = f2tf32(x);
    p.y = f2tf32(x - __uint_as_float(p.x));
    return p;
}

__device__ __forceinline__ void mma_tf32(float4& d, const uint32_t* a, const uint32_t* b) {
    asm volatile(
        "mma.sync.aligned.m16n8k8.row.col.f32.tf32.tf32.f32 "
        "{%0,%1,%2,%3}, {%4,%5,%6,%7}, {%8,%9}, {%0,%1,%2,%3};"
        : "+f"(d.x), "+f"(d.y), "+f"(d.z), "+f"(d.w)
        : "r"(a[0]), "r"(a[1]), "r"(a[2]), "r"(a[3]), "r"(b[0]), "r"(b[1]));
}

// ---------------- 3xTF32 tensor-core GEMM (champion config) -----------------
// C[n,128] = op(A)[n,KIN] @ W[KIN,128]; W is raw float, split in-kernel.
// blockIdx.y selects relation (offsets W/C and attl/attr/el/er when ELR).
// BM=128, BN=128, BK=32. 256 threads = 8 warps (4M x 2N), warp tile 32x64.
template <int KIN, bool ADD_A, bool BNA, bool ELR>
__global__ __launch_bounds__(256) void gemm_tf32_kernel(
    const float* __restrict__ A, const float* __restrict__ W, float* __restrict__ C, int n,
    const float* __restrict__ bnscale, const float* __restrict__ bnshift,
    const float* __restrict__ attl, const float* __restrict__ attr,
    float* __restrict__ el, float* __restrict__ er) {
    constexpr int KT = KIN / 32;
    constexpr int AS = 34;   // uint2 stride per A row
    constexpr int WS = 132;  // uint2 stride per W row
    __shared__ uint2 As2[128 * AS];
    __shared__ uint2 Ws2[32 * WS];

    const int rel = blockIdx.y;
    W += (size_t)rel * KIN * 128;
    C += (size_t)rel * NN * 128;
    if (ELR) {
        attl += rel * NH * HD;
        attr += rel * NH * HD;
        el += (size_t)rel * NN * NH;
        er += (size_t)rel * NN * NH;
    }

    const int tid = threadIdx.x;
    const int wid = tid >> 5;
    const int lane = tid & 31;
    const int wr = wid & 3;
    const int wc = wid >> 2;
    const int gr = lane >> 2;
    const int gc = lane & 3;
    const int m0 = blockIdx.x * 128;

    float4 acc[2][8];
#pragma unroll
    for (int mt = 0; mt < 2; mt++)
#pragma unroll
        for (int nt = 0; nt < 8; nt++) acc[mt][nt] = make_float4(0.f, 0.f, 0.f, 0.f);

    float4 ra[4], rw[4];

    auto ldA = [&](int row, int col4) -> float4 {
        float4 v = make_float4(0.f, 0.f, 0.f, 0.f);
        if (m0 + row < n) v = *(const float4*)&A[(size_t)(m0 + row) * KIN + col4];
        if (BNA) {
            float4 sc = *(const float4*)&bnscale[col4];
            float4 sh = *(const float4*)&bnshift[col4];
            v.x = fmaxf(0.f, v.x * sc.x + sh.x);
            v.y = fmaxf(0.f, v.y * sc.y + sh.y);
            v.z = fmaxf(0.f, v.z * sc.z + sh.z);
            v.w = fmaxf(0.f, v.w * sc.w + sh.w);
        }
        return v;
    };

    // ---- prefetch tile 0
#pragma unroll
    for (int t = 0; t < 4; t++) {
        int f = tid + t * 256;
        int row = f >> 3, c4 = f & 7;
        ra[t] = ldA(row, c4 * 4);
        int wrow = f >> 5, wc4 = f & 31;
        rw[t] = *(const float4*)&W[(size_t)wrow * 128 + wc4 * 4];
    }

    for (int kt = 0; kt < KT; kt++) {
#pragma unroll
        for (int t = 0; t < 4; t++) {
            int f = tid + t * 256;
            int row = f >> 3, c4 = f & 7;
            uint2* p = &As2[row * AS + c4 * 4];
            p[0] = split2(ra[t].x);
            p[1] = split2(ra[t].y);
            p[2] = split2(ra[t].z);
            p[3] = split2(ra[t].w);
            int wrow = f >> 5, wc4 = f & 31;
            uint2* q = &Ws2[wrow * WS + wc4 * 4];
            q[0] = split2(rw[t].x);
            q[1] = split2(rw[t].y);
            q[2] = split2(rw[t].z);
            q[3] = split2(rw[t].w);
        }
        __syncthreads();

        if (kt + 1 < KT) {
            int kbase = (kt + 1) * 32;
#pragma unroll
            for (int t = 0; t < 4; t++) {
                int f = tid + t * 256;
                int row = f >> 3, c4 = f & 7;
                ra[t] = ldA(row, kbase + c4 * 4);
                int wrow = f >> 5, wc4 = f & 31;
                rw[t] = *(const float4*)&W[(size_t)(kbase + wrow) * 128 + wc4 * 4];
            }
        }

#pragma unroll
        for (int k8 = 0; k8 < 4; k8++) {
            int k0 = k8 * 8;
            uint32_t ah[2][4], alo[2][4];
#pragma unroll
            for (int mt = 0; mt < 2; mt++) {
                int base = wr * 32 + mt * 16;
                uint2 x00 = As2[(base + gr) * AS + k0 + gc];
                uint2 x10 = As2[(base + gr + 8) * AS + k0 + gc];
                uint2 x01 = As2[(base + gr) * AS + k0 + gc + 4];
                uint2 x11 = As2[(base + gr + 8) * AS + k0 + gc + 4];
                ah[mt][0] = x00.x; alo[mt][0] = x00.y;
                ah[mt][1] = x10.x; alo[mt][1] = x10.y;
                ah[mt][2] = x01.x; alo[mt][2] = x01.y;
                ah[mt][3] = x11.x; alo[mt][3] = x11.y;
            }
#pragma unroll
            for (int nt = 0; nt < 8; nt++) {
                int col = wc * 64 + nt * 8 + gr;
                uint2 y0 = Ws2[(k0 + gc) * WS + col];
                uint2 y1 = Ws2[(k0 + gc + 4) * WS + col];
                uint32_t bh[2] = {y0.x, y1.x};
                uint32_t bl[2] = {y0.y, y1.y};
#pragma unroll
                for (int mt = 0; mt < 2; mt++) {
                    mma_tf32(acc[mt][nt], ah[mt], bh);   // hi*hi
                    mma_tf32(acc[mt][nt], alo[mt], bh);  // lo*hi
                    mma_tf32(acc[mt][nt], ah[mt], bl);   // hi*lo
                }
            }
        }
        __syncthreads();
    }

    // ---- epilogue
#pragma unroll
    for (int mt = 0; mt < 2; mt++) {
        int row0 = m0 + wr * 32 + mt * 16 + gr;
        int row1 = row0 + 8;
#pragma unroll
        for (int nt = 0; nt < 8; nt++) {
            int col = wc * 64 + nt * 8 + 2 * gc;
            float4 v = acc[mt][nt];
            if (row0 < n) {
                float2 o = make_float2(v.x, v.y);
                if (ADD_A) {
                    float2 a = *(const float2*)&A[(size_t)row0 * KIN + col];
                    if (BNA) {
                        a.x = fmaxf(0.f, a.x * bnscale[col] + bnshift[col]);
                        a.y = fmaxf(0.f, a.y * bnscale[col + 1] + bnshift[col + 1]);
                    }
                    o.x += a.x; o.y += a.y;
                }
                *(float2*)&C[(size_t)row0 * 128 + col] = o;
            }
            if (row1 < n) {
                float2 o = make_float2(v.z, v.w);
                if (ADD_A) {
                    float2 a = *(const float2*)&A[(size_t)row1 * KIN + col];
                    if (BNA) {
                        a.x = fmaxf(0.f, a.x * bnscale[col] + bnshift[col]);
                        a.y = fmaxf(0.f, a.y * bnscale[col + 1] + bnshift[col + 1]);
                    }
                    o.x += a.x; o.y += a.y;
                }
                *(float2*)&C[(size_t)row1 * 128 + col] = o;
            }
        }
    }

    // ---- fused attention-logit epilogue
    if (ELR) {
#pragma unroll
        for (int j = 0; j < 4; j++) {
            int head = wc * 4 + j;
            const float* alh = attl + head * 16;
            const float* arh = attr + head * 16;
            float al0 = alh[2 * gc],     al1 = alh[2 * gc + 1];
            float al2 = alh[8 + 2 * gc], al3 = alh[8 + 2 * gc + 1];
            float ar0 = arh[2 * gc],     ar1 = arh[2 * gc + 1];
            float ar2 = arh[8 + 2 * gc], ar3 = arh[8 + 2 * gc + 1];
            float sl[4], sr[4];
#pragma unroll
            for (int mt = 0; mt < 2; mt++) {
                float4 v0 = acc[mt][2 * j];
                float4 v1 = acc[mt][2 * j + 1];
                sl[mt * 2 + 0] = v0.x * al0 + v0.y * al1 + v1.x * al2 + v1.y * al3;
                sl[mt * 2 + 1] = v0.z * al0 + v0.w * al1 + v1.z * al2 + v1.w * al3;
                sr[mt * 2 + 0] = v0.x * ar0 + v0.y * ar1 + v1.x * ar2 + v1.y * ar3;
                sr[mt * 2 + 1] = v0.z * ar0 + v0.w * ar1 + v1.z * ar2 + v1.w * ar3;
            }
#pragma unroll
            for (int i = 0; i < 4; i++) {
                sl[i] += __shfl_xor_sync(0xFFFFFFFFu, sl[i], 1);
                sl[i] += __shfl_xor_sync(0xFFFFFFFFu, sl[i], 2);
                sr[i] += __shfl_xor_sync(0xFFFFFFFFu, sr[i], 1);
                sr[i] += __shfl_xor_sync(0xFFFFFFFFu, sr[i], 2);
            }
            if (gc == 0) {
#pragma unroll
                for (int mt = 0; mt < 2; mt++) {
                    int r0 = m0 + wr * 32 + mt * 16 + gr;
                    int r1 = r0 + 8;
                    if (r0 < n) { el[r0 * 8 + head] = sl[mt * 2 + 0]; er[r0 * 8 + head] = sr[mt * 2 + 0]; }
                    if (r1 < n) { el[r1 * 8 + head] = sl[mt * 2 + 1]; er[r1 * 8 + head] = sr[mt * 2 + 1]; }
                }
            }
        }
    }
}

// ---------------- scalar fp32 GEMM (KOUT=32 decode head, fused BN on A) -----
template <int KIN, int KOUT, bool BNA>
__global__ void gemm_kernel(const float* __restrict__ A, const float* __restrict__ W,
                            float* __restrict__ C, int n,
                            const float* __restrict__ bnscale,
                            const float* __restrict__ bnshift) {
    constexpr int BM = 128, BK = 32;
    constexpr int TN = KOUT / 16;
    __shared__ float As[BK][BM + 4];
    __shared__ float Ws[BK][KOUT];

    const int tid = threadIdx.x;
    const int ty = tid >> 4;
    const int tx = tid & 15;
    const int m0 = blockIdx.x * BM;

    float acc[8][TN];
#pragma unroll
    for (int i = 0; i < 8; i++)
#pragma unroll
        for (int j = 0; j < TN; j++) acc[i][j] = 0.f;

    for (int kt = 0; kt < KIN; kt += BK) {
        for (int q = tid; q < (BM * BK) / 4; q += 256) {
            int row = q / (BK / 4);
            int c4 = q % (BK / 4);
            float4 v = make_float4(0.f, 0.f, 0.f, 0.f);
            if (m0 + row < n)
                v = *(const float4*)&A[(size_t)(m0 + row) * KIN + kt + c4 * 4];
            if (BNA) {
                int col = kt + c4 * 4;
                float4 sc = *(const float4*)&bnscale[col];
                float4 sh = *(const float4*)&bnshift[col];
                v.x = fmaxf(0.f, v.x * sc.x + sh.x);
                v.y = fmaxf(0.f, v.y * sc.y + sh.y);
                v.z = fmaxf(0.f, v.z * sc.z + sh.z);
                v.w = fmaxf(0.f, v.w * sc.w + sh.w);
            }
            As[c4 * 4 + 0][row] = v.x;
            As[c4 * 4 + 1][row] = v.y;
            As[c4 * 4 + 2][row] = v.z;
            As[c4 * 4 + 3][row] = v.w;
        }
        for (int q = tid; q < (BK * KOUT) / 4; q += 256) {
            int row = q / (KOUT / 4);
            int c4 = q % (KOUT / 4);
            *(float4*)&Ws[row][c4 * 4] = *(const float4*)&W[(size_t)(kt + row) * KOUT + c4 * 4];
        }
        __syncthreads();
#pragma unroll
        for (int kk = 0; kk < BK; kk++) {
            float a[8], w[TN];
#pragma unroll
            for (int i = 0; i < 8; i++) a[i] = As[kk][ty * 8 + i];
#pragma unroll
            for (int j = 0; j < TN; j++) w[j] = Ws[kk][tx * TN + j];
#pragma unroll
            for (int i = 0; i < 8; i++)
#pragma unroll
                for (int j = 0; j < TN; j++) acc[i][j] = fmaf(a[i], w[j], acc[i][j]);
        }
        __syncthreads();
    }
#pragma unroll
    for (int i = 0; i < 8; i++) {
        int row = m0 + ty * 8 + i;
        if (row < n) {
#pragma unroll
            for (int j = 0; j < TN; j++) {
                int col = tx * TN + j;
                C[(size_t)row * KOUT + col] = acc[i][j];
            }
        }
    }
}

// ---------------- BN statistics --------------------------------------------
__global__ void stats_kernel(const float* __restrict__ X, float* __restrict__ stat, int n) {
    int c = threadIdx.x;
    int row0 = blockIdx.x * 128;
    float s = 0.f, s2 = 0.f;
#pragma unroll 4
    for (int i = 0; i < 128; i++) {
        int r = row0 + i;
        if (r < n) {
            float v = X[(size_t)r * HID + c];
            s += v;
            s2 += v * v;
        }
    }
    atomicAdd(&stat[c], s);
    atomicAdd(&stat[HID + c], s2);
}

__global__ void stats_final_kernel(const float* __restrict__ stat,
                                   const float* __restrict__ gamma,
                                   const float* __restrict__ beta,
                                   float* __restrict__ scale, float* __restrict__ shift,
                                   int n) {
    int c = threadIdx.x;
    float m = stat[c] / (float)n;
    float var = stat[HID + c] / (float)n - m * m;
    float rs = rsqrtf(var + 1e-5f) * gamma[c];
    scale[c] = rs;
    shift[c] = beta[c] - m * rs;
}

// ---------------- CSR build --------------------------------------------------
__global__ void hist_kernel(const int* __restrict__ dst, int* __restrict__ deg) {
    int i = blockIdx.x * blockDim.x + threadIdx.x;
    if (i >= RR * EE) return;
    int r = i / EE;
    atomicAdd(&deg[r * NN + dst[i]], 1);
}

__global__ void scan_kernel(const int* __restrict__ deg, int* __restrict__ off) {
    const int rel = blockIdx.x;
    const int* d = deg + rel * NN;
    int* o = off + rel * (NN + 1);
    const int T = 1024;
    const int tid = threadIdx.x;
    const int CH = (NN + T - 1) / T;
    int base = tid * CH;

    int s = 0;
    for (int j = 0; j < CH; j++) {
        int idx = base + j;
        if (idx < NN) s += d[idx];
    }
    int lane = tid & 31, wid = tid >> 5;
    int v = s;
#pragma unroll
    for (int ofs = 1; ofs < 32; ofs <<= 1) {
        int t = __shfl_up_sync(0xFFFFFFFFu, v, ofs);
        if (lane >= ofs) v += t;
    }
    __shared__ int ws[32];
    if (lane == 31) ws[wid] = v;
    __syncthreads();
    if (wid == 0) {
        int w = ws[lane];
#pragma unroll
        for (int ofs = 1; ofs < 32; ofs <<= 1) {
            int t = __shfl_up_sync(0xFFFFFFFFu, w, ofs);
            if (lane >= ofs) w += t;
        }
        ws[lane] = w;
    }
    __syncthreads();
    int excl = v - s + (wid > 0 ? ws[wid - 1] : 0);

    int run = excl;
    for (int j = 0; j < CH; j++) {
        int idx = base + j;
        if (idx < NN) {
            o[idx] = run;
            run += d[idx];
        }
    }
    if (tid == T - 1) o[NN] = run;
}

__global__ void fill_kernel(const int* __restrict__ src, const int* __restrict__ dst,
                            const int* __restrict__ off, int* __restrict__ cur,
                            int* __restrict__ csrc) {
    int i = blockIdx.x * blockDim.x + threadIdx.x;
    if (i >= RR * EE) return;
    int r = i / EE;
    int d = dst[i];
    int pos = atomicAdd(&cur[r * NN + d], 1);
    csrc[(size_t)r * EE + off[r * (NN + 1) + d] + pos] = src[i];
}

// ---------------- fused GAT: both relations, online softmax, residual -------
// warp per dst node; h1 += leakyrelu(sum_r rst_r + b0 + b1, 0.01)
__global__ void gat_fused_kernel(const int* __restrict__ off, const int* __restrict__ csrc,
                                 const float* __restrict__ elA, const float* __restrict__ erA,
                                 const float* __restrict__ featA,
                                 const float* __restrict__ b0, const float* __restrict__ b1,
                                 float* __restrict__ h1) {
    const int node = blockIdx.x * (blockDim.x >> 5) + (threadIdx.x >> 5);
    const int lane = threadIdx.x & 31;
    if (node >= NN) return;

    const int h = lane >> 2;
    const int k = lane & 3;

    float4 a4 = make_float4(0.f, 0.f, 0.f, 0.f);

#pragma unroll
    for (int r = 0; r < 2; r++) {
        const int* offr = off + r * (NN + 1);
        const int* cs = csrc + (size_t)r * EE;
        const float* el = elA + (size_t)r * NN * NH;
        const float* er = erA + (size_t)r * NN * NH;
        const float* feat = featA + (size_t)r * NN * HID;

        const int beg = offr[node];
        const int end = offr[node + 1];
        const float er_h = er[node * 8 + h];

        // online max + exp-sum (single pass over edges)
        float m = -INFINITY, s = 0.f;
        for (int e = beg + k; e < end; e += 4) {
            int si = cs[e];
            float v = lrelu02(el[si * 8 + h] + er_h);
            float mn = fmaxf(m, v);
            s = s * __expf(m - mn) + __expf(v - mn);
            m = mn;
        }
        // combine across 4 sublanes — NaN-safe: factor is 0 when m == -inf
#pragma unroll
        for (int ofs = 1; ofs < 4; ofs <<= 1) {
            float om = __shfl_xor_sync(0xFFFFFFFFu, m, ofs);
            float os = __shfl_xor_sync(0xFFFFFFFFu, s, ofs);
            float mn = fmaxf(m, om);
            float f1 = (m > -INFINITY) ? __expf(m - mn) : 0.f;
            float f2 = (om > -INFINITY) ? __expf(om - mn) : 0.f;
            s = s * f1 + os * f2;
            m = mn;
        }

        float m_l = __shfl_sync(0xFFFFFFFFu, m, (lane & 7) * 4);
        float inv_l = 1.0f / __shfl_sync(0xFFFFFFFFu, s, (lane & 7) * 4);
        float er_l = (lane < 8) ? er[node * 8 + lane] : 0.f;

        const float4* feat4 = (const float4*)feat;
        for (int e = beg; e < end; e++) {
            int si = cs[e];
            float alpha = 0.f;
            if (lane < 8) {
                float v = lrelu02(el[si * 8 + lane] + er_l);
                alpha = __expf(v - m_l) * inv_l;
            }
            float a = __shfl_sync(0xFFFFFFFFu, alpha, lane >> 2);
            float4 f = feat4[(size_t)si * 32 + lane];
            a4.x = fmaf(a, f.x, a4.x);
            a4.y = fmaf(a, f.y, a4.y);
            a4.z = fmaf(a, f.z, a4.z);
            a4.w = fmaf(a, f.w, a4.w);
        }
    }

    float4 c0 = ((const float4*)b0)[lane];
    float4 c1 = ((const float4*)b1)[lane];
    float4 hv = ((const float4*)h1)[(size_t)node * 32 + lane];
    float vx = a4.x + c0.x + c1.x;
    float vy = a4.y + c0.y + c1.y;
    float vz = a4.z + c0.z + c1.z;
    float vw = a4.w + c0.w + c1.w;
    vx = vx > 0.f ? vx : 0.01f * vx;
    vy = vy > 0.f ? vy : 0.01f * vy;
    vz = vz > 0.f ? vz : 0.01f * vz;
    vw = vw > 0.f ? vw : 0.01f * vw;
    ((float4*)h1)[(size_t)node * 32 + lane] =
        make_float4(hv.x + vx, hv.y + vy, hv.z + vz, hv.w + vw);
}

// ---------------- host orchestration ----------------------------------------
extern "C" void kernel_launch(void* const* d_in, const int* in_sizes, int n_in,
                              void* d_out, int out_size) {
    const float* inputs     = (const float*)d_in[0];
    const int*   src        = (const int*)d_in[1];
    const int*   dst        = (const int*)d_in[2];
    const float* embed_w1   = (const float*)d_in[3];
    const float* embed_g    = (const float*)d_in[4];
    const float* embed_b    = (const float*)d_in[5];
    const float* embed_w2   = (const float*)d_in[6];
    const float* gat_fc     = (const float*)d_in[7];
    const float* gat_al     = (const float*)d_in[8];
    const float* gat_ar     = (const float*)d_in[9];
    const float* gat_bias   = (const float*)d_in[10];
    const float* dec_w1     = (const float*)d_in[11];
    const float* dec_g      = (const float*)d_in[12];
    const float* dec_b      = (const float*)d_in[13];
    const float* dec_w2     = (const float*)d_in[14];
    float* out = (float*)d_out;

    float *t0, *h1, *feat, *el, *er, *stat, *scale, *shift;
    int *deg, *cur, *off, *csrc;
    cudaGetSymbolAddress((void**)&t0, g_t0);
    cudaGetSymbolAddress((void**)&h1, g_h1);
    cudaGetSymbolAddress((void**)&feat, g_feat);
    cudaGetSymbolAddress((void**)&el, g_el);
    cudaGetSymbolAddress((void**)&er, g_er);
    cudaGetSymbolAddress((void**)&stat, g_stat);
    cudaGetSymbolAddress((void**)&scale, g_scale);
    cudaGetSymbolAddress((void**)&shift, g_shift);
    cudaGetSymbolAddress((void**)&deg, g_deg);
    cudaGetSymbolAddress((void**)&cur, g_cur);
    cudaGetSymbolAddress((void**)&off, g_off);
    cudaGetSymbolAddress((void**)&csrc, g_csrc);

    // side stream + fork/join events for CSR overlap (created once; host-side only)
    static cudaStream_t s2 = nullptr;
    static cudaEvent_t ev_fork = nullptr, ev_join = nullptr;
    if (s2 == nullptr) {
        cudaStreamCreateWithFlags(&s2, cudaStreamNonBlocking);
        cudaEventCreateWithFlags(&ev_fork, cudaEventDisableTiming);
        cudaEventCreateWithFlags(&ev_join, cudaEventDisableTiming);
    }

    const int gemm_grid = (NN + 127) / 128;          // 391
    const int e2_grid   = (RR * EE + 255) / 256;     // 6250
    const int gat_grid  = (NN + 7) / 8;              // 6250 (8 warps/block)

    // ---- single stat zero for both BN stages (main stream, before everything)
    cudaMemsetAsync(stat, 0, 4 * HID * sizeof(float));

    // ---- fork: CSR build on side stream, overlapped with embed chain
    cudaEventRecord(ev_fork, 0);
    cudaStreamWaitEvent(s2, ev_fork, 0);
    cudaMemsetAsync(deg, 0, RR * NN * sizeof(int), s2);
    cudaMemsetAsync(cur, 0, RR * NN * sizeof(int), s2);
    hist_kernel<<<e2_grid, 256, 0, s2>>>(dst, deg);
    scan_kernel<<<RR, 1024, 0, s2>>>(deg, off);
    fill_kernel<<<e2_grid, 256, 0, s2>>>(src, dst, off, cur, csrc);
    cudaEventRecord(ev_join, s2);

    // ---- embed: t0 = x @ w1 ; bn stats ; h1 = bn(t0) @ w2 + bn(t0)  (main stream)
    gemm_tf32_kernel<CIN, false, false, false><<<gemm_grid, 256>>>(
        inputs, embed_w1, t0, NN, nullptr, nullptr, nullptr, nullptr, nullptr, nullptr);
    stats_kernel<<<gemm_grid, 128>>>(t0, stat, NN);
    stats_final_kernel<<<1, HID>>>(stat, embed_g, embed_b, scale, shift, NN);
    gemm_tf32_kernel<HID, true, true, false><<<gemm_grid, 256>>>(
        t0, embed_w2, h1, NN, scale, shift, nullptr, nullptr, nullptr, nullptr);

    // ---- GAT layers: both-relation fc GEMM (+fused el/er), then fused edge kernel
    for (int l = 0; l < LL; l++) {
        dim3 grid2(gemm_grid, RR);
        gemm_tf32_kernel<HID, false, false, true><<<grid2, 256>>>(
            h1, gat_fc + (size_t)l * RR * HID * HID, feat, NN, nullptr, nullptr,
            gat_al + (size_t)l * RR * NH * HD, gat_ar + (size_t)l * RR * NH * HD, el, er);
        if (l == 0) {
            // join: CSR must be ready before the first edge kernel
            cudaStreamWaitEvent(0, ev_join, 0);
        }
        const float* b0 = gat_bias + (size_t)(l * RR + 0) * HID;
        const float* b1 = gat_bias + (size_t)(l * RR + 1) * HID;
        gat_fused_kernel<<<gat_grid, 256>>>(off, csrc, el, er, feat, b0, b1, h1);
    }

    // ---- decode: t0 = h1 @ w1 ; bn stats ; out = bn(t0) @ w2
    gemm_tf32_kernel<HID, false, false, false><<<gemm_grid, 256>>>(
        h1, dec_w1, t0, NN, nullptr, nullptr, nullptr, nullptr, nullptr, nullptr);
    stats_kernel<<<gemm_grid, 128>>>(t0, stat + 2 * HID, NN);
    stats_final_kernel<<<1, HID>>>(stat + 2 * HID, dec_g, dec_b, scale, shift, NN);
    gemm_kernel<HID, COUT, true><<<gemm_grid, 256>>>(t0, dec_w2, out, NN, scale, shift);
}